// round 12
// baseline (speedup 1.0000x reference)
#include <cuda_runtime.h>
#include <cuda_fp16.h>
#include <cstdint>

#define DEV_INLINE __device__ __forceinline__

// ---------------- scratch (device globals; allocation-free) ----------------
__device__ __align__(16) __half g_vt[256u * 4096u];   // V fp16
__device__ __align__(16) __half g_ut[4096u * 256u];   // U fp16
__device__ __align__(16) __half g_t [8192u * 256u];   // T fp16

// ---------------- PTX helpers ----------------
DEV_INLINE uint32_t smem_u32(const void* p) {
    uint32_t a;
    asm("{ .reg .u64 t; cvta.to.shared.u64 t, %1; cvt.u32.u64 %0, t; }"
        : "=r"(a) : "l"(p));
    return a;
}

#define CP_ASYNC16(dst, src) \
    asm volatile("cp.async.cg.shared.global [%0], [%1], 16;" :: "r"(dst), "l"(src))
#define CP_COMMIT() asm volatile("cp.async.commit_group;" ::: "memory")
#define CP_WAIT1()  asm volatile("cp.async.wait_group 1;" ::: "memory")

#define LDSM4(r, addr) \
    asm volatile("ldmatrix.sync.aligned.m8n8.x4.shared.b16 {%0,%1,%2,%3}, [%4];" \
                 : "=r"((r)[0]), "=r"((r)[1]), "=r"((r)[2]), "=r"((r)[3]) \
                 : "r"(addr))

#define MMA_F16(d, a, b) \
    asm volatile("mma.sync.aligned.m16n8k16.row.col.f32.f16.f16.f32 " \
                 "{%0,%1,%2,%3},{%4,%5,%6,%7},{%8,%9},{%0,%1,%2,%3};" \
                 : "+f"((d)[0]), "+f"((d)[1]), "+f"((d)[2]), "+f"((d)[3]) \
                 : "r"((a)[0]), "r"((a)[1]), "r"((a)[2]), "r"((a)[3]), \
                   "r"((b)[0]), "r"((b)[1]))

// ---------------- tiling constants ----------------
static constexpr int KT = 64;                          // halves per K-chunk
static constexpr int STRIDE = 72;                      // halves per smem row (pad)
// stage 1: BM=64, BN=128, NST=3
static constexpr int NST1 = 3;
static constexpr uint32_t A1_TILE_B = 64u  * STRIDE * 2u;  // 9216 B
static constexpr uint32_t B1_TILE_B = 128u * STRIDE * 2u;  // 18432 B
static constexpr uint32_t STAGE1_B  = A1_TILE_B + B1_TILE_B;  // 27648 B
static constexpr uint32_t SMEM1_SZ  = NST1 * STAGE1_B;        // 82944 B (occ 2)
// stage 2: BM=128, BN=128, NST=3
static constexpr int NST2 = 3;
static constexpr uint32_t A2_TILE_B = 128u * STRIDE * 2u;  // 18432 B
static constexpr uint32_t STAGE2_B  = 2u * A2_TILE_B;      // 36864 B
static constexpr uint32_t SMEM2_SZ  = NST2 * STAGE2_B;     // 110592 B (occ 2)

// ---------------- convert V and U to fp16 ----------------
__global__ void cvt_vu(const float* __restrict__ V, __half* __restrict__ vt,
                       const float* __restrict__ U, __half* __restrict__ ut, int n1) {
    int i = (blockIdx.x * 256 + threadIdx.x) * 4;
    const float* s; __half* d;
    if (i < n1) { s = V; d = vt; }
    else        { s = U; d = ut; i -= n1; }
    float4 v = *reinterpret_cast<const float4*>(&s[i]);
    __half2 p0 = __floats2half2_rn(v.x, v.y);
    __half2 p1 = __floats2half2_rn(v.z, v.w);
    *reinterpret_cast<__half2*>(&d[i])     = p0;
    *reinterpret_cast<__half2*>(&d[i + 2]) = p1;
}

// ---------------- Stage 1: T = x @ V^T ----------------
// x fp32 LDG -> cvt fp16 in-reg -> STS; V pre-converted.
// BM=64, BN=128, 256 thr, warp 2x4 (tile 32x32), KT=64, NST=3, occ 2.
__global__ __launch_bounds__(256, 2)
void lr_gemm_s1(const float* __restrict__ X, const __half* __restrict__ Vt,
                int K, __half* __restrict__ T) {
    extern __shared__ __align__(16) char smem[];
    const uint32_t sb = smem_u32(smem);

    const int tid  = threadIdx.x;
    const int lane = tid & 31;
    const int warp = tid >> 5;
    const int wm = warp & 1, wn = warp >> 1;
    const int m0 = blockIdx.y * 64;
    const int n0 = blockIdx.x * 128;
    const int nk = K / KT;   // 64

    // A producer: row = tid>>2 (0..63), k-offset (tid&3)*16 floats
    const int apr = tid >> 2, apk = (tid & 3) * 16;
    // B producer: row = tid>>1 (0..127), byte offset (tid&1)*64; 4x16B per thread
    const int bpr = tid >> 1, bpb = (tid & 1) * 64;

    const float*  Xb = X  + (size_t)(m0 + apr) * K + apk;
    const __half* Vb = Vt + (size_t)(n0 + bpr) * K + bpb / 2;
    const uint32_t adst = (uint32_t)(apr * STRIDE + apk) * 2;   // bytes
    const uint32_t bdst = (uint32_t)(bpr * STRIDE) * 2 + bpb;   // bytes

    auto produceB = [&](int j) {
        if (j < nk) {
            const uint32_t st = sb + (uint32_t)(j % NST1) * STAGE1_B + A1_TILE_B;
            const __half* src = Vb + (size_t)j * KT;
            CP_ASYNC16(st + bdst,      src);
            CP_ASYNC16(st + bdst + 16, src + 8);
            CP_ASYNC16(st + bdst + 32, src + 16);
            CP_ASYNC16(st + bdst + 48, src + 24);
        }
        CP_COMMIT();
    };

    float ra[16];
    auto loadA = [&](int j) {
        if (j < nk) {
            const float* p = Xb + (size_t)j * KT;
#pragma unroll
            for (int q = 0; q < 4; q++) {
                float4 v = *reinterpret_cast<const float4*>(p + q * 4);
                ra[q * 4 + 0] = v.x; ra[q * 4 + 1] = v.y;
                ra[q * 4 + 2] = v.z; ra[q * 4 + 3] = v.w;
            }
        }
    };
    auto stsA = [&](int j) {
        const uint32_t st = (uint32_t)(j % NST1) * STAGE1_B;
        uint4 v0, v1;
        __half2 p;
        p = __floats2half2_rn(ra[0],  ra[1]);  v0.x = *reinterpret_cast<uint32_t*>(&p);
        p = __floats2half2_rn(ra[2],  ra[3]);  v0.y = *reinterpret_cast<uint32_t*>(&p);
        p = __floats2half2_rn(ra[4],  ra[5]);  v0.z = *reinterpret_cast<uint32_t*>(&p);
        p = __floats2half2_rn(ra[6],  ra[7]);  v0.w = *reinterpret_cast<uint32_t*>(&p);
        p = __floats2half2_rn(ra[8],  ra[9]);  v1.x = *reinterpret_cast<uint32_t*>(&p);
        p = __floats2half2_rn(ra[10], ra[11]); v1.y = *reinterpret_cast<uint32_t*>(&p);
        p = __floats2half2_rn(ra[12], ra[13]); v1.z = *reinterpret_cast<uint32_t*>(&p);
        p = __floats2half2_rn(ra[14], ra[15]); v1.w = *reinterpret_cast<uint32_t*>(&p);
        *reinterpret_cast<uint4*>(smem + st + adst)      = v0;
        *reinterpret_cast<uint4*>(smem + st + adst + 16) = v1;
    };

    float acc[2][4][4];
#pragma unroll
    for (int mt = 0; mt < 2; mt++)
#pragma unroll
        for (int nt = 0; nt < 4; nt++)
#pragma unroll
            for (int e = 0; e < 4; e++) acc[mt][nt][e] = 0.0f;

    // ldmatrix lane offsets (bytes within a tile)
    const int lr = lane & 7, lm = lane >> 3;
    const uint32_t offA = (uint32_t)(((lm & 1) * 8 + lr) * STRIDE + (lm >> 1) * 8) * 2;
    const uint32_t offB = (uint32_t)(((lm >> 1) * 8 + lr) * STRIDE + (lm & 1) * 8) * 2;
    const uint32_t rowA = (uint32_t)(wm * 32) * STRIDE * 2;
    const uint32_t rowB = (uint32_t)(wn * 32) * STRIDE * 2;

    loadA(0);
    produceB(0);
    produceB(1);

    for (int i = 0; i < nk; i++) {
        stsA(i);               // stage i%3 A; last read at iter i-3 (barrier-protected)
        loadA(i + 1);
        CP_WAIT1();            // B group i landed
        __syncthreads();       // A STS visible; iter i-1 consumption done
        produceB(i + 2);       // B of stage (i-1)%3 — free now
        const uint32_t st = sb + (uint32_t)(i % NST1) * STAGE1_B;
        const uint32_t aB = st + rowA + offA;
        const uint32_t bB = st + A1_TILE_B + rowB + offB;
#pragma unroll
        for (int ks = 0; ks < 4; ks++) {
            const uint32_t kb = (uint32_t)ks * 16 * 2;
            uint32_t a[2][4], b[8];
            LDSM4(a[0], aB + kb);
            LDSM4(a[1], aB + kb + 16u * STRIDE * 2);
            LDSM4(&b[0], bB + kb);
            LDSM4(&b[4], bB + kb + 16u * STRIDE * 2);
#pragma unroll
            for (int mt = 0; mt < 2; mt++)
#pragma unroll
                for (int nt = 0; nt < 4; nt++)
                    MMA_F16(acc[mt][nt], a[mt], (&b[nt * 2]));
        }
    }

    // epilogue: store T as fp16
    const int er = lane >> 2, ec = (lane & 3) * 2;
#pragma unroll
    for (int nt = 0; nt < 4; nt++) {
        const int col = n0 + wn * 32 + nt * 8 + ec;
#pragma unroll
        for (int mt = 0; mt < 2; mt++) {
            const int r0g = m0 + wm * 32 + mt * 16 + er;
#pragma unroll
            for (int h = 0; h < 2; h++) {
                const int row = r0g + h * 8;
                __half2 o = __floats2half2_rn(acc[mt][nt][h * 2 + 0],
                                              acc[mt][nt][h * 2 + 1]);
                *reinterpret_cast<__half2*>(&T[(size_t)row * 256 + col]) = o;
            }
        }
    }
}

// ---------------- Stage 2: out = T @ U^T + bias ----------------
// BM=128, BN=128, 256 thr, warp tile 64x32 (2 wm x 4 wn, mt=4). KT=64, NST=3, occ 2.
__global__ __launch_bounds__(256, 2)
void lr_gemm_s2(const __half* __restrict__ At, const __half* __restrict__ Bt,
                int K, int Nout, const float* __restrict__ bias,
                float* __restrict__ Cf) {
    extern __shared__ __align__(16) char smem[];
    const uint32_t sb = smem_u32(smem);

    const int tid  = threadIdx.x;
    const int lane = tid & 31;
    const int warp = tid >> 5;
    const int wm = warp & 1, wn = warp >> 1;
    const int m0 = blockIdx.y * 128;
    const int n0 = blockIdx.x * 128;
    const int nk = K / KT;    // 4

    // producers: row = tid>>1 (0..127), byte offset (tid&1)*64; 4x16B per operand
    const int pr = tid >> 1, pb = (tid & 1) * 64;
    const __half* Ab = At + (size_t)(m0 + pr) * K + pb / 2;
    const __half* Bb = Bt + (size_t)(n0 + pr) * K + pb / 2;
    const uint32_t pdst = (uint32_t)(pr * STRIDE) * 2 + pb;

    auto produce = [&](int j) {
        if (j < nk) {
            const uint32_t st = sb + (uint32_t)(j % NST2) * STAGE2_B;
            const __half* as = Ab + (size_t)j * KT;
            const __half* bs = Bb + (size_t)j * KT;
#pragma unroll
            for (int q = 0; q < 4; q++) {
                CP_ASYNC16(st + pdst + q * 16,             as + q * 8);
                CP_ASYNC16(st + A2_TILE_B + pdst + q * 16, bs + q * 8);
            }
        }
        CP_COMMIT();
    };

    float acc[4][4][4];
#pragma unroll
    for (int mt = 0; mt < 4; mt++)
#pragma unroll
        for (int nt = 0; nt < 4; nt++)
#pragma unroll
            for (int e = 0; e < 4; e++) acc[mt][nt][e] = 0.0f;

    const int lr = lane & 7, lm = lane >> 3;
    const uint32_t offA = (uint32_t)(((lm & 1) * 8 + lr) * STRIDE + (lm >> 1) * 8) * 2;
    const uint32_t offB = (uint32_t)(((lm >> 1) * 8 + lr) * STRIDE + (lm & 1) * 8) * 2;
    const uint32_t rowA = (uint32_t)(wm * 64) * STRIDE * 2;
    const uint32_t rowB = (uint32_t)(wn * 32) * STRIDE * 2;

    produce(0);
    produce(1);

    for (int i = 0; i < nk; i++) {
        CP_WAIT1();
        __syncthreads();
        produce(i + 2);
        const uint32_t st = sb + (uint32_t)(i % NST2) * STAGE2_B;
        const uint32_t aB = st + rowA + offA;
        const uint32_t bB = st + A2_TILE_B + rowB + offB;
#pragma unroll
        for (int ks = 0; ks < 4; ks++) {
            const uint32_t kb = (uint32_t)ks * 16 * 2;
            uint32_t a[4][4], b[8];
#pragma unroll
            for (int mt = 0; mt < 4; mt++)
                LDSM4(a[mt], aB + kb + (uint32_t)mt * 16u * STRIDE * 2);
            LDSM4(&b[0], bB + kb);
            LDSM4(&b[4], bB + kb + 16u * STRIDE * 2);
#pragma unroll
            for (int mt = 0; mt < 4; mt++)
#pragma unroll
                for (int nt = 0; nt < 4; nt++)
                    MMA_F16(acc[mt][nt], a[mt], (&b[nt * 2]));
        }
    }

    const int er = lane >> 2, ec = (lane & 3) * 2;
#pragma unroll
    for (int nt = 0; nt < 4; nt++) {
        const int col = n0 + wn * 32 + nt * 8 + ec;
        const float b0 = bias[col], b1 = bias[col + 1];
#pragma unroll
        for (int mt = 0; mt < 4; mt++) {
            const int r0g = m0 + wm * 64 + mt * 16 + er;
#pragma unroll
            for (int h = 0; h < 2; h++) {
                const int row = r0g + h * 8;
                float2 o = make_float2(acc[mt][nt][h * 2 + 0] + b0,
                                       acc[mt][nt][h * 2 + 1] + b1);
                *reinterpret_cast<float2*>(&Cf[(size_t)row * Nout + col]) = o;
            }
        }
    }
}

// ---------------- launch ----------------
extern "C" void kernel_launch(void* const* d_in, const int* in_sizes, int n_in,
                              void* d_out, int out_size) {
    const float* x    = (const float*)d_in[0];   // [8192, 4096]
    const float* U    = (const float*)d_in[1];   // [4096, 256]
    const float* V    = (const float*)d_in[2];   // [256, 4096]
    const float* bias = (const float*)d_in[3];   // [4096]
    float* out = (float*)d_out;                  // [8192, 4096]

    __half *vt, *ut, *T;
    cudaGetSymbolAddress((void**)&vt, g_vt);
    cudaGetSymbolAddress((void**)&ut, g_ut);
    cudaGetSymbolAddress((void**)&T,  g_t);

    cudaFuncSetAttribute(lr_gemm_s1, cudaFuncAttributeMaxDynamicSharedMemorySize, SMEM1_SZ);
    cudaFuncSetAttribute(lr_gemm_s2, cudaFuncAttributeMaxDynamicSharedMemorySize, SMEM2_SZ);

    // convert V and U to fp16 (one tiny launch)
    const int n1 = 256 * 4096;
    cvt_vu<<<(2 * n1 / 4) / 256, 256>>>(V, vt, U, ut, n1);

    // Stage 1: T[8192,256] = x @ V^T (K=4096): 256 CTAs, occ 2
    lr_gemm_s1<<<dim3(256 / 128, 8192 / 64), 256, SMEM1_SZ>>>(x, vt, 4096, T);

    // Stage 2: out[8192,4096] = T @ U^T + bias (K=256): 2048 CTAs, occ 2
    lr_gemm_s2<<<dim3(4096 / 128, 8192 / 128), 256, SMEM2_SZ>>>(
        T, ut, 256, 4096, bias, out);
}